// round 12
// baseline (speedup 1.0000x reference)
#include <cuda_runtime.h>
#include <cstdint>

#define NATOM 8192
#define EMAX  131072
#define NW    16
#define NPARA 13
#define NFEAT 208   // 13*16
#define NORB  128
#define NHID  64
#define CH    16    // edges per staged chunk

// ---------------- device scratch (no allocs allowed) ----------------
__device__ __align__(16)  int   g_count[NATOM];
__device__ __align__(16)  int   g_offset[NATOM + 1];
__device__ __align__(16)  int   g_cursor[NATOM];
__device__ __align__(16)  int2  g_ejd[EMAX];                 // CSR slot -> {j, dcut}
__device__ __align__(256) float g_edge[(size_t)EMAX * 32];   // CSR-ordered AoS 128B/edge
__device__ __align__(256) float g_WsumA[(size_t)NATOM * NFEAT];
__device__ __align__(256) float g_WsumB[(size_t)NATOM * NFEAT];
__device__ __align__(256) float g_coeff[(size_t)NATOM * NW];
__device__ __align__(256) float g_density[(size_t)NATOM * NORB];

// resolved pointers for the three size-64 inputs (rs / inta / params_p)
__device__ const float* g_rs_p;
__device__ const float* g_inta_p;
__device__ const float* g_par_p;

// ------ classify size-64 trio by value + zero the histogram ---------
__global__ void k_classify(const float* a, const float* b, const float* c) {
    int tid = threadIdx.x;  // 128
    __shared__ float mx[3];
    if (tid < 96) {
        int w = tid >> 5, lane = tid & 31;
        const float* p = (w == 0) ? a : (w == 1) ? b : c;
        float m = fmaxf(p[lane], p[lane + 32]);
#pragma unroll
        for (int off = 16; off; off >>= 1)
            m = fmaxf(m, __shfl_xor_sync(0xffffffffu, m, off));
        if (lane == 0) mx[w] = m;
    }
    for (int i = tid; i < NATOM; i += 128) g_count[i] = 0;
    __syncthreads();
    if (tid == 0) {
        const float* p[3] = {a, b, c};
        int inta_i = 0;
        if (mx[1] < 0.f) inta_i = 1;
        if (mx[2] < 0.f) inta_i = 2;
        int r0 = (inta_i == 0) ? 1 : 0;
        int r1 = (inta_i == 2) ? 1 : 2;
        int rs_i, pp_i;
        if (mx[r0] > mx[r1]) { rs_i = r0; pp_i = r1; }
        else                 { rs_i = r1; pp_i = r0; }
        g_inta_p = p[inta_i];
        g_rs_p   = p[rs_i];
        g_par_p  = p[pp_i];
    }
}

// ------ merged: histogram of i_idx + coeff init ---------------------
__global__ void k_prep(const int* __restrict__ neigh,
                       const int* __restrict__ species, int E) {
    int t = blockIdx.x * blockDim.x + threadIdx.x;
    if (t < E) {
        int i = neigh[t];
        if ((unsigned)i < NATOM) atomicAdd(&g_count[i], 1);
    }
    if (t < NATOM * NW) {
        int i = t >> 4, k = t & 15;
        g_coeff[t] = g_par_p[species[i] * NW + k];
    }
}

// ------ single-block shuffle scan over 8192 counts ------------------
__global__ void __launch_bounds__(1024) k_scan() {
    int tid = threadIdx.x;
    int lane = tid & 31, wid = tid >> 5;
    int4 c0 = *(const int4*)(g_count + tid * 8);
    int4 c1 = *(const int4*)(g_count + tid * 8 + 4);
    int v[8] = {c0.x, c0.y, c0.z, c0.w, c1.x, c1.y, c1.z, c1.w};
    int s = 0;
#pragma unroll
    for (int u = 0; u < 8; u++) s += v[u];
    int incl = s;
#pragma unroll
    for (int off = 1; off < 32; off <<= 1) {
        int n = __shfl_up_sync(0xffffffffu, incl, off);
        if (lane >= off) incl += n;
    }
    __shared__ int wexcl[32];
    __shared__ int wtot[32];
    if (lane == 31) wtot[wid] = incl;
    __syncthreads();
    if (wid == 0) {
        int t = wtot[lane];
        int ti = t;
#pragma unroll
        for (int off = 1; off < 32; off <<= 1) {
            int n = __shfl_up_sync(0xffffffffu, ti, off);
            if (lane >= off) ti += n;
        }
        wexcl[lane] = ti - t;
    }
    __syncthreads();
    int run = wexcl[wid] + (incl - s);
    int o[8];
#pragma unroll
    for (int u = 0; u < 8; u++) { o[u] = run; run += v[u]; }
    int4 o0 = {o[0], o[1], o[2], o[3]};
    int4 o1 = {o[4], o[5], o[6], o[7]};
    *(int4*)(g_offset + tid * 8) = o0;
    *(int4*)(g_offset + tid * 8 + 4) = o1;
    *(int4*)(g_cursor + tid * 8) = o0;
    *(int4*)(g_cursor + tid * 8 + 4) = o1;
    if (tid == 1023) g_offset[NATOM] = run;
}

// ------ per-edge geometry, stored DIRECTLY at CSR slot --------------
// row layout (32 floats): [0..1]=0, [2..14]=ang[13] (ang[0]=dcut), [15]=0,
// [16..31]=rad[16]
#define EB 128
__global__ void __launch_bounds__(EB) k_edges(
        const float* __restrict__ cart, const float* __restrict__ shifts,
        const int* __restrict__ species, const int* __restrict__ neigh, int E) {
    __shared__ float st[EB * 33];
    __shared__ int spos[EB];
    int tid = threadIdx.x;
    int e = blockIdx.x * EB + tid;
    float* row = st + tid * 33;
    if (e < E) {
        const float* rs   = g_rs_p;
        const float* inta = g_inta_p;
        int i = neigh[e];
        int j = neigh[E + e];
        float dx = cart[i * 3 + 0] - cart[j * 3 + 0] - shifts[e * 3 + 0];
        float dy = cart[i * 3 + 1] - cart[j * 3 + 1] - shifts[e * 3 + 1];
        float dz = cart[i * 3 + 2] - cart[j * 3 + 2] - shifts[e * 3 + 2];
        float dist = sqrtf(dx * dx + dy * dy + dz * dz);
        int pos = atomicAdd(&g_cursor[i], 1);   // start L2 atomic early
        float inv = 1.0f / dist;
        float ux = dx * inv, uy = dy * inv, uz = dz * inv;
        float c = 0.5f * cosf(dist * 0.6283185307179586f) + 0.5f;  // pi/5
        float dcut = c * c;
        int sp = species[j];
        row[0] = 0.f; row[1] = 0.f;
        row[2] = dcut;
        row[3] = dcut * ux; row[4] = dcut * uy; row[5] = dcut * uz;
        float u[3] = {ux, uy, uz};
#pragma unroll
        for (int a = 0; a < 3; a++)
#pragma unroll
            for (int b = 0; b < 3; b++)
                row[6 + a * 3 + b] = dcut * u[a] * u[b];
        row[15] = 0.f;
#pragma unroll
        for (int k = 0; k < NW; k++) {
            float t = dist - rs[sp * NW + k];
            row[16 + k] = expf(inta[sp * NW + k] * t * t);
        }
        spos[tid] = pos;
        g_ejd[pos] = make_int2(j, __float_as_int(dcut));
    } else {
        spos[tid] = -1;
    }
    __syncthreads();
    // 8 threads per row write one 128B row to its CSR slot. Shared stride is
    // 33 floats -> source not 16B aligned: read scalars, store aligned float4.
    int r = tid >> 3, q = tid & 7;
    for (; r < EB; r += 16) {
        int pos = spos[r];
        if (pos >= 0) {
            const float* src = st + r * 33 + q * 4;
            float4 v = {src[0], src[1], src[2], src[3]};
            *(float4*)(g_edge + (size_t)pos * 32 + q * 4) = v;
        }
    }
}

// ---------------- fused per-atom: staged gather + density -----------
// Per 16-edge chunk: (1) ALL 256 threads bulk-load edge rows + coeff[j] +
// Wsum[j] rows into shared (independent LDG.128s -> one memory latency per
// chunk); (2) 52 threads compute from shared (zero global latency).
// PASS 0: WsumA = F; PASS 1: WsumB = WsumA + F; PASS 2: no Wsum write.
template <int PASS>
__global__ void __launch_bounds__(256, 4)
k_atom(const float* __restrict__ ef, const float* __restrict__ ef_para,
       const float* __restrict__ hyper, float* __restrict__ dens_final) {
    int i = blockIdx.x;
    int tid = threadIdx.x;
    __shared__ float s_ed[CH * 32];      // 2 KB  edge rows
    __shared__ float s_cf[CH * 16];      // 1 KB  coeff[j]
    __shared__ float s_ws[CH * NFEAT];   // 13 KB Wsum[j] (PASS>0)
    __shared__ float F_sh[NFEAT];
    const float* WsumIn = (PASS == 1) ? g_WsumA : g_WsumB;
    float* WsumOut = (PASS == 0) ? g_WsumA : g_WsumB;
    int start = g_offset[i], end = g_offset[i + 1];

    // accumulators (threads 0..51); base ef_orb0 term
    int p = min(tid >> 2, 12);
    int kq = (tid & 3) << 2;
    float ax = 0.f, ay = 0.f, az = 0.f, aw = 0.f;
    if (tid < 52) {
        int b = i >> 9;   // A = 512 atoms per batch
        float e0 = ef[b * 3], e1 = ef[b * 3 + 1], e2 = ef[b * 3 + 2];
        float angef;
        if (p == 0) angef = 1.f;
        else if (p < 4) angef = (p == 1) ? e0 : ((p == 2) ? e1 : e2);
        else {
            int q = p - 4;
            float u0 = (q < 3) ? e0 : ((q < 6) ? e1 : e2);
            float u1 = (q % 3 == 0) ? e0 : ((q % 3 == 1) ? e1 : e2);
            angef = u0 * u1;
        }
        float4 epr = *(const float4*)(ef_para + kq);
        ax = angef * epr.x; ay = angef * epr.y;
        az = angef * epr.z; aw = angef * epr.w;
    }

    for (int c0 = start; c0 < end; c0 += CH) {
        int n = min(CH, end - c0);
        __syncthreads();   // protect shared from overwrite while in use
        // ---- bulk load: edge rows (n*8 float4) ----
        for (int idx = tid; idx < n * 8; idx += 256) {
            int e = idx >> 3, q = idx & 7;
            float4 v = *(const float4*)(g_edge + (size_t)(c0 + e) * 32 + q * 4);
            *(float4*)(s_ed + e * 32 + q * 4) = v;
        }
        // ---- coeff rows (n*4 float4) ----
        for (int idx = tid; idx < n * 4; idx += 256) {
            int e = idx >> 2, q = idx & 3;
            int j = g_ejd[c0 + e].x;
            float4 v = *(const float4*)(g_coeff + (size_t)j * NW + q * 4);
            *(float4*)(s_cf + e * 16 + q * 4) = v;
        }
        // ---- Wsum rows (n*52 float4) ----
        if (PASS > 0) {
            for (int idx = tid; idx < n * 52; idx += 256) {
                int e = idx / 52, q = idx - e * 52;
                int j = g_ejd[c0 + e].x;
                float4 v = *(const float4*)(WsumIn + (size_t)j * NFEAT + q * 4);
                *(float4*)(s_ws + e * NFEAT + q * 4) = v;
            }
        }
        __syncthreads();
        // ---- compute from shared ----
        if (tid < 52) {
            for (int e = 0; e < n; e++) {
                const float* ed = s_ed + e * 32;
                float dcut = ed[2];
                float ang = ed[2 + p];
                float4 rad = *(const float4*)(ed + 16 + kq);
                float4 cf = *(const float4*)(s_cf + e * 16 + kq);
                float ox = ang * rad.x, oy = ang * rad.y;
                float oz = ang * rad.z, ow = ang * rad.w;
                if (PASS > 0) {
                    float4 w = *(const float4*)(s_ws + e * NFEAT + p * 16 + kq);
                    ox += dcut * w.x; oy += dcut * w.y;
                    oz += dcut * w.z; ow += dcut * w.w;
                }
                ax += cf.x * ox; ay += cf.y * oy;
                az += cf.z * oz; aw += cf.w * ow;
            }
        }
    }
    __syncthreads();
    // ---- write features + Wsum update ----
    if (tid < 52) {
        int fb = p * 16 + kq;
        float4 v = {ax, ay, az, aw};
        *(float4*)(F_sh + fb) = v;
        if (PASS < 2) {
            float4 o = v;
            if (PASS == 1) {
                float4 pr = *(const float4*)(WsumIn + (size_t)i * NFEAT + fb);
                o.x += pr.x; o.y += pr.y; o.z += pr.z; o.w += pr.w;
            }
            *(float4*)(WsumOut + (size_t)i * NFEAT + fb) = o;
        }
    }
    __syncthreads();

    // ---- density: 64 threads, 2 orbit cols each; H loaded once/(l,kk) ----
    if (tid < 64) {
        int m = tid * 2;
        float* dens_out = (PASS == 2) ? dens_final : g_density;
        float dx = 0.f, dy = 0.f;
        // l = 0 (pp = 0)
        {
            float hx = 0.f, hy = 0.f;
#pragma unroll
            for (int kk = 0; kk < NW; kk++) {
                float2 h2 = *(const float2*)(hyper + kk * NORB + m);
                float e = F_sh[kk];
                hx += e * h2.x; hy += e * h2.y;
            }
            dx += hx * hx; dy += hy * hy;
        }
        // l = 1 (pp = 1..3)
        {
            float hx[3] = {0.f, 0.f, 0.f}, hy[3] = {0.f, 0.f, 0.f};
#pragma unroll
            for (int kk = 0; kk < NW; kk++) {
                float2 h2 = *(const float2*)(hyper + NW * NORB + kk * NORB + m);
#pragma unroll
                for (int q = 0; q < 3; q++) {
                    float e = F_sh[(1 + q) * NW + kk];
                    hx[q] += e * h2.x; hy[q] += e * h2.y;
                }
            }
#pragma unroll
            for (int q = 0; q < 3; q++) { dx += hx[q] * hx[q]; dy += hy[q] * hy[q]; }
        }
        // l = 2 (pp = 4..12)
        {
            float hx[9], hy[9];
#pragma unroll
            for (int q = 0; q < 9; q++) { hx[q] = 0.f; hy[q] = 0.f; }
#pragma unroll
            for (int kk = 0; kk < NW; kk++) {
                float2 h2 = *(const float2*)(hyper + 2 * NW * NORB + kk * NORB + m);
#pragma unroll
                for (int q = 0; q < 9; q++) {
                    float e = F_sh[(4 + q) * NW + kk];
                    hx[q] += e * h2.x; hy[q] += e * h2.y;
                }
            }
#pragma unroll
            for (int q = 0; q < 9; q++) { dx += hx[q] * hx[q]; dy += hy[q] * hy[q]; }
        }
        float2 o = {dx, dy};
        *(float2*)(dens_out + (size_t)i * NORB + m) = o;
    }
}

// ---------------- MLP: coeff += tanh(density@W1+b1)@W2 --------------
// 8 atoms per block, 512 threads. Static smem = 39936 B -> 4 blocks/SM.
__global__ void __launch_bounds__(512)
k_mlp(const float* __restrict__ W1, const float* __restrict__ b1,
      const float* __restrict__ W2) {
    __shared__ float W1T[NHID * 132];   // padded transpose, 33 KB
    __shared__ float dsh[8 * NORB];     // 4 KB
    __shared__ float hsh[8 * NHID];     // 2 KB
    int tid = threadIdx.x;
    int i0 = blockIdx.x * 8;
    for (int idx = tid; idx < NORB * NHID; idx += 512) {
        int k = idx >> 6, h = idx & 63;
        W1T[h * 132 + k] = W1[idx];
    }
    for (int idx = tid; idx < 8 * NORB; idx += 512)
        dsh[idx] = g_density[(size_t)i0 * NORB + idx];
    __syncthreads();
    int a = tid >> 6, h = tid & 63;
    float acc = b1[h];
    const float4* w4 = (const float4*)(W1T + h * 132);
    const float4* d4 = (const float4*)(dsh + a * NORB);
#pragma unroll
    for (int q = 0; q < 32; q++) {
        float4 w = w4[q], d = d4[q];
        acc += w.x * d.x + w.y * d.y + w.z * d.z + w.w * d.w;
    }
    hsh[a * NHID + h] = tanhf(acc);
    __syncthreads();
    if (h < NW) {
        float delta = 0.f;
#pragma unroll
        for (int hh = 0; hh < NHID; hh++)
            delta += hsh[a * NHID + hh] * __ldg(&W2[hh * NW + h]);
        g_coeff[(i0 + a) * NW + h] += delta;
    }
}

// ---------------- launch --------------------------------------------
extern "C" void kernel_launch(void* const* d_in, const int* in_sizes, int n_in,
                              void* d_out, int out_size) {
    const float *cart = 0, *ef = 0, *shifts = 0, *ef_para = 0, *hyper = 0;
    const float *oc_w1 = 0, *oc_b1 = 0, *oc_w2 = 0;
    const int *neigh = 0, *species = 0;   // int32 (JAX x64 disabled)
    const float* trio[3] = {0, 0, 0};
    int ntrio = 0;
    for (int t = 0; t < n_in; t++) {
        int s = in_sizes[t];
        const void* p = d_in[t];
        switch (s) {
            case 24576:  cart    = (const float*)p; break;
            case 48:     ef      = (const float*)p; break;
            case 393216: shifts  = (const float*)p; break;
            case 16:     ef_para = (const float*)p; break;
            case 6144:   hyper   = (const float*)p; break;
            case 16384:  oc_w1   = (const float*)p; break;
            case 128:    oc_b1   = (const float*)p; break;
            case 2048:   oc_w2   = (const float*)p; break;
            case 262144: neigh   = (const int*)p; break;
            case 8192:   species = (const int*)p; break;
            case 64:     if (ntrio < 3) trio[ntrio++] = (const float*)p; break;
            default: break;
        }
    }
    if (!cart || !ef || !shifts || !ef_para || !hyper || !oc_w1 || !oc_b1 ||
        !oc_w2 || !neigh || !species || ntrio != 3) {
        cart    = (const float*)d_in[0];
        ef      = (const float*)d_in[1];
        shifts  = (const float*)d_in[2];
        trio[0] = (const float*)d_in[3];
        trio[1] = (const float*)d_in[4];
        trio[2] = (const float*)d_in[5];
        ef_para = (const float*)d_in[6];
        hyper   = (const float*)d_in[7];
        oc_w1   = (const float*)d_in[8];
        oc_b1   = (const float*)d_in[9];
        oc_w2   = (const float*)d_in[10];
        neigh   = (const int*)d_in[11];
        species = (const int*)d_in[12];
    }
    int E = EMAX;

    k_classify<<<1, 128>>>(trio[0], trio[1], trio[2]);
    k_prep<<<(E + 255) / 256, 256>>>(neigh, species, E);
    k_scan<<<1, 1024>>>();
    // Diagnostic mini-pass (4th launch = ncu window). Reads prior-replay
    // scratch (deterministic); its outputs are overwritten by the real
    // pass 0. Measures the new staged kernel's per-block critical path.
    k_atom<0><<<148, 256>>>(ef, ef_para, hyper, nullptr);
    k_edges<<<(E + EB - 1) / EB, EB>>>(cart, shifts, species, neigh, E);

    k_atom<0><<<NATOM, 256>>>(ef, ef_para, hyper, nullptr);
    k_mlp<<<NATOM / 8, 512>>>(oc_w1, oc_b1, oc_w2);
    k_atom<1><<<NATOM, 256>>>(ef, ef_para, hyper, nullptr);
    k_mlp<<<NATOM / 8, 512>>>(oc_w1 + NORB * NHID, oc_b1 + NHID, oc_w2 + NHID * NW);
    k_atom<2><<<NATOM, 256>>>(ef, ef_para, hyper, (float*)d_out);
}

// round 13
// speedup vs baseline: 1.2954x; 1.2954x over previous
#include <cuda_runtime.h>
#include <cstdint>

#define NATOM 8192
#define EMAX  131072
#define NW    16
#define NPARA 13
#define NFEAT 208   // 13*16
#define NORB  128
#define NHID  64

// ---------------- device scratch (no allocs allowed) ----------------
__device__ __align__(16)  int   g_count[NATOM];      // zero-init; self-cleaned by k_scan
__device__ __align__(16)  int   g_offset[NATOM + 1];
__device__ __align__(16)  int   g_cursor[NATOM];
__device__ __align__(16)  int2  g_ejd[EMAX];                 // CSR slot -> {j, dcut}
__device__ __align__(256) float g_edge[(size_t)EMAX * 32];   // CSR-ordered AoS 128B/edge
__device__ __align__(256) float g_WsumA[(size_t)NATOM * NFEAT];
__device__ __align__(256) float g_WsumB[(size_t)NATOM * NFEAT];
__device__ __align__(256) float g_coeff[(size_t)NATOM * NW];
__device__ __align__(256) float g_density[(size_t)NATOM * NORB];

// resolved pointers for rs / inta (consumed by k_edges)
__device__ const float* g_rs_p;
__device__ const float* g_inta_p;
__device__ const float* g_par_p;

// ------ prep: per-block trio classification + histogram + coeff -----
// Every block classifies the three size-64 arrays locally (cheap); block 0
// publishes rs/inta pointers for k_edges. inta = all negative; rs has
// max > 2 w.h.p.; params_p ~ N(1,0.01) max ~1.4.
__global__ void __launch_bounds__(256) k_prep(
        const float* a, const float* b, const float* c,
        const int* __restrict__ neigh, const int* __restrict__ species, int E) {
    __shared__ float mx[3];
    int tid = threadIdx.x;
    if (tid < 96) {
        int w = tid >> 5, lane = tid & 31;
        const float* p = (w == 0) ? a : (w == 1) ? b : c;
        float m = fmaxf(p[lane], p[lane + 32]);
#pragma unroll
        for (int off = 16; off; off >>= 1)
            m = fmaxf(m, __shfl_xor_sync(0xffffffffu, m, off));
        if (lane == 0) mx[w] = m;
    }
    __syncthreads();
    int inta_i = 0;
    if (mx[1] < 0.f) inta_i = 1;
    if (mx[2] < 0.f) inta_i = 2;
    int r0 = (inta_i == 0) ? 1 : 0;
    int r1 = (inta_i == 2) ? 1 : 2;
    int rs_i, pp_i;
    if (mx[r0] > mx[r1]) { rs_i = r0; pp_i = r1; }
    else                 { rs_i = r1; pp_i = r0; }
    const float* ptr[3] = {a, b, c};
    const float* par = ptr[pp_i];
    if (blockIdx.x == 0 && tid == 0) {
        g_inta_p = ptr[inta_i];
        g_rs_p   = ptr[rs_i];
        g_par_p  = par;
    }
    int t = blockIdx.x * 256 + tid;
    if (t < E) {
        int i = neigh[t];
        if ((unsigned)i < NATOM) atomicAdd(&g_count[i], 1);
    }
    if (t < NATOM * NW) {
        int i = t >> 4, k = t & 15;
        g_coeff[t] = par[species[i] * NW + k];
    }
}

// ------ single-block shuffle scan; re-zeroes g_count for next replay
__global__ void __launch_bounds__(1024) k_scan() {
    int tid = threadIdx.x;
    int lane = tid & 31, wid = tid >> 5;
    int4 c0 = *(const int4*)(g_count + tid * 8);
    int4 c1 = *(const int4*)(g_count + tid * 8 + 4);
    int v[8] = {c0.x, c0.y, c0.z, c0.w, c1.x, c1.y, c1.z, c1.w};
    int s = 0;
#pragma unroll
    for (int u = 0; u < 8; u++) s += v[u];
    int incl = s;
#pragma unroll
    for (int off = 1; off < 32; off <<= 1) {
        int n = __shfl_up_sync(0xffffffffu, incl, off);
        if (lane >= off) incl += n;
    }
    __shared__ int wexcl[32];
    __shared__ int wtot[32];
    if (lane == 31) wtot[wid] = incl;
    __syncthreads();
    if (wid == 0) {
        int t = wtot[lane];
        int ti = t;
#pragma unroll
        for (int off = 1; off < 32; off <<= 1) {
            int n = __shfl_up_sync(0xffffffffu, ti, off);
            if (lane >= off) ti += n;
        }
        wexcl[lane] = ti - t;
    }
    __syncthreads();
    int run = wexcl[wid] + (incl - s);
    int o[8];
#pragma unroll
    for (int u = 0; u < 8; u++) { o[u] = run; run += v[u]; }
    int4 o0 = {o[0], o[1], o[2], o[3]};
    int4 o1 = {o[4], o[5], o[6], o[7]};
    *(int4*)(g_offset + tid * 8) = o0;
    *(int4*)(g_offset + tid * 8 + 4) = o1;
    *(int4*)(g_cursor + tid * 8) = o0;
    *(int4*)(g_cursor + tid * 8 + 4) = o1;
    if (tid == 1023) g_offset[NATOM] = run;
    // self-clean: each thread zeroes exactly the counts it read
    int4 z = {0, 0, 0, 0};
    *(int4*)(g_count + tid * 8) = z;
    *(int4*)(g_count + tid * 8 + 4) = z;
}

// ------ per-edge geometry, stored DIRECTLY at CSR slot --------------
// row layout (32 floats): [0..1]=0, [2..14]=ang[13] (ang[0]=dcut), [15]=0,
// [16..31]=rad[16]
#define EB 128
__global__ void __launch_bounds__(EB) k_edges(
        const float* __restrict__ cart, const float* __restrict__ shifts,
        const int* __restrict__ species, const int* __restrict__ neigh, int E) {
    __shared__ float st[EB * 33];
    __shared__ int spos[EB];
    int tid = threadIdx.x;
    int e = blockIdx.x * EB + tid;
    float* row = st + tid * 33;
    if (e < E) {
        const float* rs   = g_rs_p;
        const float* inta = g_inta_p;
        int i = neigh[e];
        int j = neigh[E + e];
        float dx = cart[i * 3 + 0] - cart[j * 3 + 0] - shifts[e * 3 + 0];
        float dy = cart[i * 3 + 1] - cart[j * 3 + 1] - shifts[e * 3 + 1];
        float dz = cart[i * 3 + 2] - cart[j * 3 + 2] - shifts[e * 3 + 2];
        float dist = sqrtf(dx * dx + dy * dy + dz * dz);
        int pos = atomicAdd(&g_cursor[i], 1);   // start L2 atomic early
        float inv = 1.0f / dist;
        float ux = dx * inv, uy = dy * inv, uz = dz * inv;
        float c = 0.5f * cosf(dist * 0.6283185307179586f) + 0.5f;  // pi/5
        float dcut = c * c;
        int sp = species[j];
        row[0] = 0.f; row[1] = 0.f;
        row[2] = dcut;
        row[3] = dcut * ux; row[4] = dcut * uy; row[5] = dcut * uz;
        float u[3] = {ux, uy, uz};
#pragma unroll
        for (int a = 0; a < 3; a++)
#pragma unroll
            for (int b = 0; b < 3; b++)
                row[6 + a * 3 + b] = dcut * u[a] * u[b];
        row[15] = 0.f;
#pragma unroll
        for (int k = 0; k < NW; k++) {
            float t = dist - rs[sp * NW + k];
            row[16 + k] = expf(inta[sp * NW + k] * t * t);
        }
        spos[tid] = pos;
        g_ejd[pos] = make_int2(j, __float_as_int(dcut));
    } else {
        spos[tid] = -1;
    }
    __syncthreads();
    // 8 threads per row write one 128B row to its CSR slot. Shared stride is
    // 33 floats -> source not 16B aligned: read scalars, store aligned float4.
    int r = tid >> 3, q = tid & 7;
    for (; r < EB; r += 16) {
        int pos = spos[r];
        if (pos >= 0) {
            const float* src = st + r * 33 + q * 4;
            float4 v = {src[0], src[1], src[2], src[3]};
            *(float4*)(g_edge + (size_t)pos * 32 + q * 4) = v;
        }
    }
}

// ---------------- per-atom gather + hyper einsum + density ----------
// 64 threads per atom. Edge loop UNROLLED BY 4 (branch-free tail) so four
// edges' independent loads are in flight per warp (MLP ~12 vs ~3).
// PASS 0: WsumA = F; PASS 1: WsumB = WsumA + F; PASS 2: no Wsum write.
template <int PASS>
__global__ void __launch_bounds__(64, 8)
k_atom(const float* __restrict__ ef, const float* __restrict__ ef_para,
       const float* __restrict__ hyper, float* __restrict__ dens_final) {
    int i = blockIdx.x;
    int tid = threadIdx.x;
    int lane = tid & 31;
    __shared__ float sh[NFEAT];
    const float* WsumIn = (PASS == 1) ? g_WsumA : g_WsumB;
    float* WsumOut = (PASS == 0) ? g_WsumA : g_WsumB;
    int start = g_offset[i], end = g_offset[i + 1];

    // gather phase: all 64 threads run the loop; only tid<52 store results
    {
        int p = min(tid >> 2, 12);
        int kq = (tid & 3) << 2;
        int b = i >> 9;  // A = 512 atoms per batch
        float e0 = ef[b * 3], e1 = ef[b * 3 + 1], e2 = ef[b * 3 + 2];
        float angef;
        if (p == 0) angef = 1.f;
        else if (p < 4) angef = (p == 1) ? e0 : ((p == 2) ? e1 : e2);
        else {
            int q = p - 4;
            float u0 = (q < 3) ? e0 : ((q < 6) ? e1 : e2);
            float u1 = (q % 3 == 0) ? e0 : ((q % 3 == 1) ? e1 : e2);
            angef = u0 * u1;
        }
        float4 epr = *(const float4*)(ef_para + kq);
        float ax = angef * epr.x, ay = angef * epr.y;
        float az = angef * epr.z, aw = angef * epr.w;

        for (int base = start; base < end; base += 32) {
            int cnt = min(32, end - base);
            int jj = 0; float dd = 0.f;
            if (base + lane < end) {
                int2 t = g_ejd[base + lane];
                jj = t.x; dd = __int_as_float(t.y);
            }
            for (int s0 = 0; s0 < cnt; s0 += 4) {
#pragma unroll
                for (int u = 0; u < 4; u++) {
                    int ss = s0 + u;
                    bool valid = ss < cnt;
                    int sc = valid ? ss : cnt - 1;
                    int j = __shfl_sync(0xffffffffu, jj, sc);
                    float dcut = __int_as_float(
                        __shfl_sync(0xffffffffu, __float_as_int(dd), sc));
                    const float* ed = g_edge + (size_t)(base + sc) * 32;
                    float ang = ed[2 + p];
                    float4 rad = *(const float4*)(ed + 16 + kq);
                    float4 cf = *(const float4*)(g_coeff + j * NW + kq);
                    if (!valid) { ang = 0.f; dcut = 0.f; }
                    float ox = ang * rad.x, oy = ang * rad.y;
                    float oz = ang * rad.z, ow = ang * rad.w;
                    if (PASS > 0) {
                        float4 w = *(const float4*)(WsumIn + (size_t)j * NFEAT + p * 16 + kq);
                        ox += dcut * w.x; oy += dcut * w.y;
                        oz += dcut * w.z; ow += dcut * w.w;
                    }
                    ax += cf.x * ox; ay += cf.y * oy;
                    az += cf.z * oz; aw += cf.w * ow;
                }
            }
        }
        if (tid < 52) {
            int fb = p * 16 + kq;
            float4 v = {ax, ay, az, aw};
            *(float4*)(sh + fb) = v;
            if (PASS < 2) {
                float4 o = v;
                if (PASS == 1) {
                    float4 pr = *(const float4*)(WsumIn + (size_t)i * NFEAT + fb);
                    o.x += pr.x; o.y += pr.y; o.z += pr.z; o.w += pr.w;
                }
                *(float4*)(WsumOut + (size_t)i * NFEAT + fb) = o;
            }
        }
    }
    __syncthreads();

    // density phase: 64 threads x 2 orbit cols; H loaded once per (l,kk)
    // (l=2 split into 3 chunks of 3 pp's to bound live registers)
    {
        int m = tid * 2;
        float* dens_out = (PASS == 2) ? dens_final : g_density;
        float dx = 0.f, dy = 0.f;
        // l = 0 (pp = 0)
        {
            float hx = 0.f, hy = 0.f;
#pragma unroll
            for (int kk = 0; kk < NW; kk++) {
                float2 h2 = *(const float2*)(hyper + kk * NORB + m);
                float e = sh[kk];
                hx += e * h2.x; hy += e * h2.y;
            }
            dx += hx * hx; dy += hy * hy;
        }
        // l = 1 (pp = 1..3)
        {
            float hx[3] = {0.f, 0.f, 0.f}, hy[3] = {0.f, 0.f, 0.f};
#pragma unroll
            for (int kk = 0; kk < NW; kk++) {
                float2 h2 = *(const float2*)(hyper + NW * NORB + kk * NORB + m);
#pragma unroll
                for (int q = 0; q < 3; q++) {
                    float e = sh[(1 + q) * NW + kk];
                    hx[q] += e * h2.x; hy[q] += e * h2.y;
                }
            }
#pragma unroll
            for (int q = 0; q < 3; q++) { dx += hx[q] * hx[q]; dy += hy[q] * hy[q]; }
        }
        // l = 2 (pp = 4..12), 3 chunks of 3
#pragma unroll
        for (int g = 0; g < 3; g++) {
            float hx[3] = {0.f, 0.f, 0.f}, hy[3] = {0.f, 0.f, 0.f};
#pragma unroll
            for (int kk = 0; kk < NW; kk++) {
                float2 h2 = *(const float2*)(hyper + 2 * NW * NORB + kk * NORB + m);
#pragma unroll
                for (int q = 0; q < 3; q++) {
                    float e = sh[(4 + g * 3 + q) * NW + kk];
                    hx[q] += e * h2.x; hy[q] += e * h2.y;
                }
            }
#pragma unroll
            for (int q = 0; q < 3; q++) { dx += hx[q] * hx[q]; dy += hy[q] * hy[q]; }
        }
        float2 o = {dx, dy};
        *(float2*)(dens_out + (size_t)i * NORB + m) = o;
    }
}

// ---------------- MLP: coeff += tanh(density@W1+b1)@W2 --------------
// 8 atoms per block, 512 threads. Static smem = 39936 B -> 4 blocks/SM.
__global__ void __launch_bounds__(512)
k_mlp(const float* __restrict__ W1, const float* __restrict__ b1,
      const float* __restrict__ W2) {
    __shared__ float W1T[NHID * 132];   // padded transpose, 33 KB
    __shared__ float dsh[8 * NORB];     // 4 KB
    __shared__ float hsh[8 * NHID];     // 2 KB
    int tid = threadIdx.x;
    int i0 = blockIdx.x * 8;
    for (int idx = tid; idx < NORB * NHID; idx += 512) {
        int k = idx >> 6, h = idx & 63;
        W1T[h * 132 + k] = W1[idx];
    }
    for (int idx = tid; idx < 8 * NORB; idx += 512)
        dsh[idx] = g_density[(size_t)i0 * NORB + idx];
    __syncthreads();
    int a = tid >> 6, h = tid & 63;
    float acc = b1[h];
    const float4* w4 = (const float4*)(W1T + h * 132);
    const float4* d4 = (const float4*)(dsh + a * NORB);
#pragma unroll
    for (int q = 0; q < 32; q++) {
        float4 w = w4[q], d = d4[q];
        acc += w.x * d.x + w.y * d.y + w.z * d.z + w.w * d.w;
    }
    hsh[a * NHID + h] = tanhf(acc);
    __syncthreads();
    if (h < NW) {
        float delta = 0.f;
#pragma unroll
        for (int hh = 0; hh < NHID; hh++)
            delta += hsh[a * NHID + hh] * __ldg(&W2[hh * NW + h]);
        g_coeff[(i0 + a) * NW + h] += delta;
    }
}

// ---------------- launch --------------------------------------------
extern "C" void kernel_launch(void* const* d_in, const int* in_sizes, int n_in,
                              void* d_out, int out_size) {
    const float *cart = 0, *ef = 0, *shifts = 0, *ef_para = 0, *hyper = 0;
    const float *oc_w1 = 0, *oc_b1 = 0, *oc_w2 = 0;
    const int *neigh = 0, *species = 0;   // int32 (JAX x64 disabled)
    const float* trio[3] = {0, 0, 0};
    int ntrio = 0;
    for (int t = 0; t < n_in; t++) {
        int s = in_sizes[t];
        const void* p = d_in[t];
        switch (s) {
            case 24576:  cart    = (const float*)p; break;
            case 48:     ef      = (const float*)p; break;
            case 393216: shifts  = (const float*)p; break;
            case 16:     ef_para = (const float*)p; break;
            case 6144:   hyper   = (const float*)p; break;
            case 16384:  oc_w1   = (const float*)p; break;
            case 128:    oc_b1   = (const float*)p; break;
            case 2048:   oc_w2   = (const float*)p; break;
            case 262144: neigh   = (const int*)p; break;
            case 8192:   species = (const int*)p; break;
            case 64:     if (ntrio < 3) trio[ntrio++] = (const float*)p; break;
            default: break;
        }
    }
    if (!cart || !ef || !shifts || !ef_para || !hyper || !oc_w1 || !oc_b1 ||
        !oc_w2 || !neigh || !species || ntrio != 3) {
        cart    = (const float*)d_in[0];
        ef      = (const float*)d_in[1];
        shifts  = (const float*)d_in[2];
        trio[0] = (const float*)d_in[3];
        trio[1] = (const float*)d_in[4];
        trio[2] = (const float*)d_in[5];
        ef_para = (const float*)d_in[6];
        hyper   = (const float*)d_in[7];
        oc_w1   = (const float*)d_in[8];
        oc_b1   = (const float*)d_in[9];
        oc_w2   = (const float*)d_in[10];
        neigh   = (const int*)d_in[11];
        species = (const int*)d_in[12];
    }
    int E = EMAX;

    k_prep<<<(E + 255) / 256, 256>>>(trio[0], trio[1], trio[2], neigh, species, E);
    k_scan<<<1, 1024>>>();
    k_edges<<<(E + EB - 1) / EB, EB>>>(cart, shifts, species, neigh, E);

    k_atom<0><<<NATOM, 64>>>(ef, ef_para, hyper, nullptr);   // 4th launch (ncu)
    k_mlp<<<NATOM / 8, 512>>>(oc_w1, oc_b1, oc_w2);
    k_atom<1><<<NATOM, 64>>>(ef, ef_para, hyper, nullptr);
    k_mlp<<<NATOM / 8, 512>>>(oc_w1 + NORB * NHID, oc_b1 + NHID, oc_w2 + NHID * NW);
    k_atom<2><<<NATOM, 64>>>(ef, ef_para, hyper, (float*)d_out);
}

// round 14
// speedup vs baseline: 1.3458x; 1.0389x over previous
#include <cuda_runtime.h>
#include <cstdint>

#define NATOM 8192
#define EMAX  131072
#define EPAD  (EMAX + 3 * NATOM)   // CSR padded to multiple-of-4 per atom
#define NW    16
#define NPARA 13
#define NFEAT 208   // 13*16
#define NORB  128
#define NHID  64

// ---------------- device scratch (no allocs allowed) ----------------
// NOTE: __device__ globals are zero-initialized at module load. Pad slots in
// g_edge / g_ejd are NEVER written -> they read as all-zero (ang=0, dcut=0,
// j=0), contributing exactly 0 to the gather. This makes CSR padding free.
__device__ __align__(16)  int   g_count[NATOM];      // self-cleaned by k_scan
__device__ __align__(16)  int   g_offset[NATOM + 1]; // PADDED prefix
__device__ __align__(16)  int   g_cursor[NATOM];
__device__ __align__(16)  int2  g_ejd[EPAD];                 // CSR slot -> {j, dcut}
__device__ __align__(256) float g_edge[(size_t)EPAD * 32];   // CSR-ordered AoS 128B/edge
__device__ __align__(256) float g_WsumA[(size_t)NATOM * NFEAT];
__device__ __align__(256) float g_WsumB[(size_t)NATOM * NFEAT];
__device__ __align__(256) float g_coeff[(size_t)NATOM * NW];
__device__ __align__(256) float g_density[(size_t)NATOM * NORB];

// resolved pointers for rs / inta / params_p
__device__ const float* g_rs_p;
__device__ const float* g_inta_p;
__device__ const float* g_par_p;

// ------ prep: per-block trio classification + histogram + coeff -----
__global__ void __launch_bounds__(256) k_prep(
        const float* a, const float* b, const float* c,
        const int* __restrict__ neigh, const int* __restrict__ species, int E) {
    __shared__ float mx[3];
    int tid = threadIdx.x;
    if (tid < 96) {
        int w = tid >> 5, lane = tid & 31;
        const float* p = (w == 0) ? a : (w == 1) ? b : c;
        float m = fmaxf(p[lane], p[lane + 32]);
#pragma unroll
        for (int off = 16; off; off >>= 1)
            m = fmaxf(m, __shfl_xor_sync(0xffffffffu, m, off));
        if (lane == 0) mx[w] = m;
    }
    __syncthreads();
    int inta_i = 0;
    if (mx[1] < 0.f) inta_i = 1;
    if (mx[2] < 0.f) inta_i = 2;
    int r0 = (inta_i == 0) ? 1 : 0;
    int r1 = (inta_i == 2) ? 1 : 2;
    int rs_i, pp_i;
    if (mx[r0] > mx[r1]) { rs_i = r0; pp_i = r1; }
    else                 { rs_i = r1; pp_i = r0; }
    const float* ptr[3] = {a, b, c};
    const float* par = ptr[pp_i];
    if (blockIdx.x == 0 && tid == 0) {
        g_inta_p = ptr[inta_i];
        g_rs_p   = ptr[rs_i];
        g_par_p  = par;
    }
    int t = blockIdx.x * 256 + tid;
    if (t < E) {
        int i = neigh[t];
        if ((unsigned)i < NATOM) atomicAdd(&g_count[i], 1);
    }
    if (t < NATOM * NW) {
        int i = t >> 4, k = t & 15;
        g_coeff[t] = par[species[i] * NW + k];
    }
}

// ------ single-block shuffle scan (PADDED counts); self-cleans ------
__global__ void __launch_bounds__(1024) k_scan() {
    int tid = threadIdx.x;
    int lane = tid & 31, wid = tid >> 5;
    int4 c0 = *(const int4*)(g_count + tid * 8);
    int4 c1 = *(const int4*)(g_count + tid * 8 + 4);
    int v[8] = {c0.x, c0.y, c0.z, c0.w, c1.x, c1.y, c1.z, c1.w};
    int s = 0;
#pragma unroll
    for (int u = 0; u < 8; u++) {
        v[u] = (v[u] + 3) & ~3;   // pad each atom's slot count to mult of 4
        s += v[u];
    }
    int incl = s;
#pragma unroll
    for (int off = 1; off < 32; off <<= 1) {
        int n = __shfl_up_sync(0xffffffffu, incl, off);
        if (lane >= off) incl += n;
    }
    __shared__ int wexcl[32];
    __shared__ int wtot[32];
    if (lane == 31) wtot[wid] = incl;
    __syncthreads();
    if (wid == 0) {
        int t = wtot[lane];
        int ti = t;
#pragma unroll
        for (int off = 1; off < 32; off <<= 1) {
            int n = __shfl_up_sync(0xffffffffu, ti, off);
            if (lane >= off) ti += n;
        }
        wexcl[lane] = ti - t;
    }
    __syncthreads();
    int run = wexcl[wid] + (incl - s);
    int o[8];
#pragma unroll
    for (int u = 0; u < 8; u++) { o[u] = run; run += v[u]; }
    int4 o0 = {o[0], o[1], o[2], o[3]};
    int4 o1 = {o[4], o[5], o[6], o[7]};
    *(int4*)(g_offset + tid * 8) = o0;
    *(int4*)(g_offset + tid * 8 + 4) = o1;
    *(int4*)(g_cursor + tid * 8) = o0;   // fill starts at padded offset
    *(int4*)(g_cursor + tid * 8 + 4) = o1;
    if (tid == 1023) g_offset[NATOM] = run;
    int4 z = {0, 0, 0, 0};
    *(int4*)(g_count + tid * 8) = z;
    *(int4*)(g_count + tid * 8 + 4) = z;
}

// ------ per-edge geometry, stored DIRECTLY at CSR slot --------------
// row layout (32 floats): [0..1]=0, [2..14]=ang[13] (ang[0]=dcut), [15]=0,
// [16..31]=rad[16]
#define EB 128
__global__ void __launch_bounds__(EB) k_edges(
        const float* __restrict__ cart, const float* __restrict__ shifts,
        const int* __restrict__ species, const int* __restrict__ neigh, int E) {
    __shared__ float st[EB * 33];
    __shared__ int spos[EB];
    int tid = threadIdx.x;
    int e = blockIdx.x * EB + tid;
    float* row = st + tid * 33;
    if (e < E) {
        const float* rs   = g_rs_p;
        const float* inta = g_inta_p;
        int i = neigh[e];
        int j = neigh[E + e];
        float dx = cart[i * 3 + 0] - cart[j * 3 + 0] - shifts[e * 3 + 0];
        float dy = cart[i * 3 + 1] - cart[j * 3 + 1] - shifts[e * 3 + 1];
        float dz = cart[i * 3 + 2] - cart[j * 3 + 2] - shifts[e * 3 + 2];
        float dist = sqrtf(dx * dx + dy * dy + dz * dz);
        int pos = atomicAdd(&g_cursor[i], 1);   // start L2 atomic early
        float inv = 1.0f / dist;
        float ux = dx * inv, uy = dy * inv, uz = dz * inv;
        float c = 0.5f * cosf(dist * 0.6283185307179586f) + 0.5f;  // pi/5
        float dcut = c * c;
        int sp = species[j];
        row[0] = 0.f; row[1] = 0.f;
        row[2] = dcut;
        row[3] = dcut * ux; row[4] = dcut * uy; row[5] = dcut * uz;
        float u[3] = {ux, uy, uz};
#pragma unroll
        for (int a = 0; a < 3; a++)
#pragma unroll
            for (int b = 0; b < 3; b++)
                row[6 + a * 3 + b] = dcut * u[a] * u[b];
        row[15] = 0.f;
#pragma unroll
        for (int k = 0; k < NW; k++) {
            float t = dist - rs[sp * NW + k];
            row[16 + k] = expf(inta[sp * NW + k] * t * t);
        }
        spos[tid] = pos;
        g_ejd[pos] = make_int2(j, __float_as_int(dcut));
    } else {
        spos[tid] = -1;
    }
    __syncthreads();
    // 8 threads per row write one 128B row to its CSR slot. Shared stride is
    // 33 floats -> source not 16B aligned: read scalars, store aligned float4.
    int r = tid >> 3, q = tid & 7;
    for (; r < EB; r += 16) {
        int pos = spos[r];
        if (pos >= 0) {
            const float* src = st + r * 33 + q * 4;
            float4 v = {src[0], src[1], src[2], src[3]};
            *(float4*)(g_edge + (size_t)pos * 32 + q * 4) = v;
        }
    }
}

// ---------------- per-atom gather + hyper einsum + density ----------
// 64 threads per atom. CSR is padded to multiple-of-4 slots (pad rows are
// all-zero -> contribute 0), so the edge loop is clean fixed-trip groups of
// 4 with NO tail logic. {j,dcut} read as warp-uniform g_ejd loads with a
// next-group prefetch. launch_bounds(64,12): 85-reg cap -> 24 warps/SM.
// PASS 0: WsumA = F; PASS 1: WsumB = WsumA + F; PASS 2: no Wsum write.
template <int PASS>
__global__ void __launch_bounds__(64, 12)
k_atom(const float* __restrict__ ef, const float* __restrict__ ef_para,
       const float* __restrict__ hyper, float* __restrict__ dens_final) {
    int i = blockIdx.x;
    int tid = threadIdx.x;
    __shared__ float sh[NFEAT];
    const float* WsumIn = (PASS == 1) ? g_WsumA : g_WsumB;
    float* WsumOut = (PASS == 0) ? g_WsumA : g_WsumB;
    int start = g_offset[i], end = g_offset[i + 1];

    // gather phase
    {
        int p = min(tid >> 2, 12);
        int kq = (tid & 3) << 2;
        int b = i >> 9;  // A = 512 atoms per batch
        float e0 = ef[b * 3], e1 = ef[b * 3 + 1], e2 = ef[b * 3 + 2];
        float angef;
        if (p == 0) angef = 1.f;
        else if (p < 4) angef = (p == 1) ? e0 : ((p == 2) ? e1 : e2);
        else {
            int q = p - 4;
            float u0 = (q < 3) ? e0 : ((q < 6) ? e1 : e2);
            float u1 = (q % 3 == 0) ? e0 : ((q % 3 == 1) ? e1 : e2);
            angef = u0 * u1;
        }
        float4 epr = *(const float4*)(ef_para + kq);
        float ax = angef * epr.x, ay = angef * epr.y;
        float az = angef * epr.z, aw = angef * epr.w;

        int2 n0, n1, n2, n3;
        if (start < end) {
            n0 = g_ejd[start];     n1 = g_ejd[start + 1];
            n2 = g_ejd[start + 2]; n3 = g_ejd[start + 3];
        }
        for (int s = start; s < end; s += 4) {
            int2 c0 = n0, c1 = n1, c2 = n2, c3 = n3;
            int sn = s + 4;
            if (sn < end) {   // prefetch next group (hides ejd->cf chain)
                n0 = g_ejd[sn];     n1 = g_ejd[sn + 1];
                n2 = g_ejd[sn + 2]; n3 = g_ejd[sn + 3];
            }
            const float* edb = g_edge + (size_t)s * 32;
#pragma unroll
            for (int u = 0; u < 4; u++) {
                int2 cu = (u == 0) ? c0 : (u == 1) ? c1 : (u == 2) ? c2 : c3;
                int j = cu.x;
                float dcut = __int_as_float(cu.y);
                const float* ed = edb + u * 32;
                float ang = ed[2 + p];
                float4 rad = *(const float4*)(ed + 16 + kq);
                float4 cf = *(const float4*)(g_coeff + j * NW + kq);
                float ox = ang * rad.x, oy = ang * rad.y;
                float oz = ang * rad.z, ow = ang * rad.w;
                if (PASS > 0) {
                    float4 w = *(const float4*)(WsumIn + (size_t)j * NFEAT + p * 16 + kq);
                    ox += dcut * w.x; oy += dcut * w.y;
                    oz += dcut * w.z; ow += dcut * w.w;
                }
                ax += cf.x * ox; ay += cf.y * oy;
                az += cf.z * oz; aw += cf.w * ow;
            }
        }
        if (tid < 52) {
            int fb = p * 16 + kq;
            float4 v = {ax, ay, az, aw};
            *(float4*)(sh + fb) = v;
            if (PASS < 2) {
                float4 o = v;
                if (PASS == 1) {
                    float4 pr = *(const float4*)(WsumIn + (size_t)i * NFEAT + fb);
                    o.x += pr.x; o.y += pr.y; o.z += pr.z; o.w += pr.w;
                }
                *(float4*)(WsumOut + (size_t)i * NFEAT + fb) = o;
            }
        }
    }
    __syncthreads();

    // density phase: 64 threads x 2 orbit cols; H loaded once per (l,kk)
    // (l=2 split into 3 chunks of 3 pp's to bound live registers)
    {
        int m = tid * 2;
        float* dens_out = (PASS == 2) ? dens_final : g_density;
        float dx = 0.f, dy = 0.f;
        {
            float hx = 0.f, hy = 0.f;
#pragma unroll
            for (int kk = 0; kk < NW; kk++) {
                float2 h2 = *(const float2*)(hyper + kk * NORB + m);
                float e = sh[kk];
                hx += e * h2.x; hy += e * h2.y;
            }
            dx += hx * hx; dy += hy * hy;
        }
        {
            float hx[3] = {0.f, 0.f, 0.f}, hy[3] = {0.f, 0.f, 0.f};
#pragma unroll
            for (int kk = 0; kk < NW; kk++) {
                float2 h2 = *(const float2*)(hyper + NW * NORB + kk * NORB + m);
#pragma unroll
                for (int q = 0; q < 3; q++) {
                    float e = sh[(1 + q) * NW + kk];
                    hx[q] += e * h2.x; hy[q] += e * h2.y;
                }
            }
#pragma unroll
            for (int q = 0; q < 3; q++) { dx += hx[q] * hx[q]; dy += hy[q] * hy[q]; }
        }
#pragma unroll
        for (int g = 0; g < 3; g++) {
            float hx[3] = {0.f, 0.f, 0.f}, hy[3] = {0.f, 0.f, 0.f};
#pragma unroll
            for (int kk = 0; kk < NW; kk++) {
                float2 h2 = *(const float2*)(hyper + 2 * NW * NORB + kk * NORB + m);
#pragma unroll
                for (int q = 0; q < 3; q++) {
                    float e = sh[(4 + g * 3 + q) * NW + kk];
                    hx[q] += e * h2.x; hy[q] += e * h2.y;
                }
            }
#pragma unroll
            for (int q = 0; q < 3; q++) { dx += hx[q] * hx[q]; dy += hy[q] * hy[q]; }
        }
        float2 o = {dx, dy};
        *(float2*)(dens_out + (size_t)i * NORB + m) = o;
    }
}

// ---------------- MLP: coeff += tanh(density@W1+b1)@W2 --------------
// 8 atoms per block, 512 threads. Static smem = 39936 B -> 4 blocks/SM.
__global__ void __launch_bounds__(512)
k_mlp(const float* __restrict__ W1, const float* __restrict__ b1,
      const float* __restrict__ W2) {
    __shared__ float W1T[NHID * 132];   // padded transpose, 33 KB
    __shared__ float dsh[8 * NORB];     // 4 KB
    __shared__ float hsh[8 * NHID];     // 2 KB
    int tid = threadIdx.x;
    int i0 = blockIdx.x * 8;
    for (int idx = tid; idx < NORB * NHID; idx += 512) {
        int k = idx >> 6, h = idx & 63;
        W1T[h * 132 + k] = W1[idx];
    }
    for (int idx = tid; idx < 8 * NORB; idx += 512)
        dsh[idx] = g_density[(size_t)i0 * NORB + idx];
    __syncthreads();
    int a = tid >> 6, h = tid & 63;
    float acc = b1[h];
    const float4* w4 = (const float4*)(W1T + h * 132);
    const float4* d4 = (const float4*)(dsh + a * NORB);
#pragma unroll
    for (int q = 0; q < 32; q++) {
        float4 w = w4[q], d = d4[q];
        acc += w.x * d.x + w.y * d.y + w.z * d.z + w.w * d.w;
    }
    hsh[a * NHID + h] = tanhf(acc);
    __syncthreads();
    if (h < NW) {
        float delta = 0.f;
#pragma unroll
        for (int hh = 0; hh < NHID; hh++)
            delta += hsh[a * NHID + hh] * __ldg(&W2[hh * NW + h]);
        g_coeff[(i0 + a) * NW + h] += delta;
    }
}

// ---------------- launch --------------------------------------------
extern "C" void kernel_launch(void* const* d_in, const int* in_sizes, int n_in,
                              void* d_out, int out_size) {
    const float *cart = 0, *ef = 0, *shifts = 0, *ef_para = 0, *hyper = 0;
    const float *oc_w1 = 0, *oc_b1 = 0, *oc_w2 = 0;
    const int *neigh = 0, *species = 0;   // int32 (JAX x64 disabled)
    const float* trio[3] = {0, 0, 0};
    int ntrio = 0;
    for (int t = 0; t < n_in; t++) {
        int s = in_sizes[t];
        const void* p = d_in[t];
        switch (s) {
            case 24576:  cart    = (const float*)p; break;
            case 48:     ef      = (const float*)p; break;
            case 393216: shifts  = (const float*)p; break;
            case 16:     ef_para = (const float*)p; break;
            case 6144:   hyper   = (const float*)p; break;
            case 16384:  oc_w1   = (const float*)p; break;
            case 128:    oc_b1   = (const float*)p; break;
            case 2048:   oc_w2   = (const float*)p; break;
            case 262144: neigh   = (const int*)p; break;
            case 8192:   species = (const int*)p; break;
            case 64:     if (ntrio < 3) trio[ntrio++] = (const float*)p; break;
            default: break;
        }
    }
    if (!cart || !ef || !shifts || !ef_para || !hyper || !oc_w1 || !oc_b1 ||
        !oc_w2 || !neigh || !species || ntrio != 3) {
        cart    = (const float*)d_in[0];
        ef      = (const float*)d_in[1];
        shifts  = (const float*)d_in[2];
        trio[0] = (const float*)d_in[3];
        trio[1] = (const float*)d_in[4];
        trio[2] = (const float*)d_in[5];
        ef_para = (const float*)d_in[6];
        hyper   = (const float*)d_in[7];
        oc_w1   = (const float*)d_in[8];
        oc_b1   = (const float*)d_in[9];
        oc_w2   = (const float*)d_in[10];
        neigh   = (const int*)d_in[11];
        species = (const int*)d_in[12];
    }
    int E = EMAX;

    k_prep<<<(E + 255) / 256, 256>>>(trio[0], trio[1], trio[2], neigh, species, E);
    k_scan<<<1, 1024>>>();
    k_edges<<<(E + EB - 1) / EB, EB>>>(cart, shifts, species, neigh, E);

    k_atom<0><<<NATOM, 64>>>(ef, ef_para, hyper, nullptr);   // 4th launch (ncu)
    k_mlp<<<NATOM / 8, 512>>>(oc_w1, oc_b1, oc_w2);
    k_atom<1><<<NATOM, 64>>>(ef, ef_para, hyper, nullptr);
    k_mlp<<<NATOM / 8, 512>>>(oc_w1 + NORB * NHID, oc_b1 + NHID, oc_w2 + NHID * NW);
    k_atom<2><<<NATOM, 64>>>(ef, ef_para, hyper, (float*)d_out);
}

// round 15
// speedup vs baseline: 1.4227x; 1.0571x over previous
#include <cuda_runtime.h>
#include <cstdint>

#define NATOM 8192
#define EMAX  131072
#define EPAD  (EMAX + 3 * NATOM)   // CSR padded to multiple-of-4 per atom
#define NW    16
#define NPU   10                   // unique angular comps: 1 + 3 + 6 (sym l=2)
#define NFU   160                  // NPU * NW
#define NORB  128
#define NHID  64

// ---------------- device scratch (no allocs allowed) ----------------
// __device__ globals are zero-initialized; pad slots in g_edge/g_ejd are
// never written -> read as zeros -> contribute exactly 0 to the gather.
__device__ __align__(16)  int   g_count[NATOM];      // self-cleaned by k_scan
__device__ __align__(16)  int   g_offset[NATOM + 1]; // PADDED prefix
__device__ __align__(16)  int   g_cursor[NATOM];
__device__ __align__(16)  int2  g_ejd[EPAD];                 // CSR slot -> {j, dcut}
__device__ __align__(256) float g_edge[(size_t)EPAD * 32];   // CSR-ordered AoS 128B/edge
__device__ __align__(256) float g_WsumA[(size_t)NATOM * NFU];
__device__ __align__(256) float g_WsumB[(size_t)NATOM * NFU];
__device__ __align__(256) float g_coeff[(size_t)NATOM * NW];
__device__ __align__(256) float g_density[(size_t)NATOM * NORB];

__device__ const float* g_rs_p;
__device__ const float* g_inta_p;
__device__ const float* g_par_p;

// ------ prep: per-block trio classification + histogram + coeff -----
__global__ void __launch_bounds__(256) k_prep(
        const float* a, const float* b, const float* c,
        const int* __restrict__ neigh, const int* __restrict__ species, int E) {
    __shared__ float mx[3];
    int tid = threadIdx.x;
    if (tid < 96) {
        int w = tid >> 5, lane = tid & 31;
        const float* p = (w == 0) ? a : (w == 1) ? b : c;
        float m = fmaxf(p[lane], p[lane + 32]);
#pragma unroll
        for (int off = 16; off; off >>= 1)
            m = fmaxf(m, __shfl_xor_sync(0xffffffffu, m, off));
        if (lane == 0) mx[w] = m;
    }
    __syncthreads();
    int inta_i = 0;
    if (mx[1] < 0.f) inta_i = 1;
    if (mx[2] < 0.f) inta_i = 2;
    int r0 = (inta_i == 0) ? 1 : 0;
    int r1 = (inta_i == 2) ? 1 : 2;
    int rs_i, pp_i;
    if (mx[r0] > mx[r1]) { rs_i = r0; pp_i = r1; }
    else                 { rs_i = r1; pp_i = r0; }
    const float* ptr[3] = {a, b, c};
    const float* par = ptr[pp_i];
    if (blockIdx.x == 0 && tid == 0) {
        g_inta_p = ptr[inta_i];
        g_rs_p   = ptr[rs_i];
        g_par_p  = par;
    }
    int t = blockIdx.x * 256 + tid;
    if (t < E) {
        int i = neigh[t];
        if ((unsigned)i < NATOM) atomicAdd(&g_count[i], 1);
    }
    if (t < NATOM * NW) {
        int i = t >> 4, k = t & 15;
        g_coeff[t] = par[species[i] * NW + k];
    }
}

// ------ single-block shuffle scan (PADDED counts); self-cleans ------
__global__ void __launch_bounds__(1024) k_scan() {
    int tid = threadIdx.x;
    int lane = tid & 31, wid = tid >> 5;
    int4 c0 = *(const int4*)(g_count + tid * 8);
    int4 c1 = *(const int4*)(g_count + tid * 8 + 4);
    int v[8] = {c0.x, c0.y, c0.z, c0.w, c1.x, c1.y, c1.z, c1.w};
    int s = 0;
#pragma unroll
    for (int u = 0; u < 8; u++) {
        v[u] = (v[u] + 3) & ~3;
        s += v[u];
    }
    int incl = s;
#pragma unroll
    for (int off = 1; off < 32; off <<= 1) {
        int n = __shfl_up_sync(0xffffffffu, incl, off);
        if (lane >= off) incl += n;
    }
    __shared__ int wexcl[32];
    __shared__ int wtot[32];
    if (lane == 31) wtot[wid] = incl;
    __syncthreads();
    if (wid == 0) {
        int t = wtot[lane];
        int ti = t;
#pragma unroll
        for (int off = 1; off < 32; off <<= 1) {
            int n = __shfl_up_sync(0xffffffffu, ti, off);
            if (lane >= off) ti += n;
        }
        wexcl[lane] = ti - t;
    }
    __syncthreads();
    int run = wexcl[wid] + (incl - s);
    int o[8];
#pragma unroll
    for (int u = 0; u < 8; u++) { o[u] = run; run += v[u]; }
    int4 o0 = {o[0], o[1], o[2], o[3]};
    int4 o1 = {o[4], o[5], o[6], o[7]};
    *(int4*)(g_offset + tid * 8) = o0;
    *(int4*)(g_offset + tid * 8 + 4) = o1;
    *(int4*)(g_cursor + tid * 8) = o0;
    *(int4*)(g_cursor + tid * 8 + 4) = o1;
    if (tid == 1023) g_offset[NATOM] = run;
    int4 z = {0, 0, 0, 0};
    *(int4*)(g_count + tid * 8) = z;
    *(int4*)(g_count + tid * 8 + 4) = z;
}

// ------ per-edge geometry, stored DIRECTLY at CSR slot --------------
// row layout (32 floats): [0..1]=0, [2..11]=ang_u[10] (ang_u[0]=dcut,
// [1..3]=dcut*u, [4..9]=dcut*{xx,xy,xz,yy,yz,zz}), [12..15]=0, [16..31]=rad
#define EB 128
__global__ void __launch_bounds__(EB) k_edges(
        const float* __restrict__ cart, const float* __restrict__ shifts,
        const int* __restrict__ species, const int* __restrict__ neigh, int E) {
    __shared__ float st[EB * 33];
    __shared__ int spos[EB];
    int tid = threadIdx.x;
    int e = blockIdx.x * EB + tid;
    float* row = st + tid * 33;
    if (e < E) {
        const float* rs   = g_rs_p;
        const float* inta = g_inta_p;
        int i = neigh[e];
        int j = neigh[E + e];
        float dx = cart[i * 3 + 0] - cart[j * 3 + 0] - shifts[e * 3 + 0];
        float dy = cart[i * 3 + 1] - cart[j * 3 + 1] - shifts[e * 3 + 1];
        float dz = cart[i * 3 + 2] - cart[j * 3 + 2] - shifts[e * 3 + 2];
        float dist = sqrtf(dx * dx + dy * dy + dz * dz);
        int pos = atomicAdd(&g_cursor[i], 1);
        float inv = 1.0f / dist;
        float ux = dx * inv, uy = dy * inv, uz = dz * inv;
        float c = 0.5f * cosf(dist * 0.6283185307179586f) + 0.5f;  // pi/5
        float dcut = c * c;
        int sp = species[j];
        row[0] = 0.f; row[1] = 0.f;
        row[2] = dcut;
        row[3] = dcut * ux; row[4] = dcut * uy; row[5] = dcut * uz;
        row[6] = dcut * ux * ux;  // xx
        row[7] = dcut * ux * uy;  // xy
        row[8] = dcut * ux * uz;  // xz
        row[9] = dcut * uy * uy;  // yy
        row[10] = dcut * uy * uz; // yz
        row[11] = dcut * uz * uz; // zz
        row[12] = 0.f; row[13] = 0.f; row[14] = 0.f; row[15] = 0.f;
#pragma unroll
        for (int k = 0; k < NW; k++) {
            float t = dist - rs[sp * NW + k];
            row[16 + k] = expf(inta[sp * NW + k] * t * t);
        }
        spos[tid] = pos;
        g_ejd[pos] = make_int2(j, __float_as_int(dcut));
    } else {
        spos[tid] = -1;
    }
    __syncthreads();
    int r = tid >> 3, q = tid & 7;
    for (; r < EB; r += 16) {
        int pos = spos[r];
        if (pos >= 0) {
            const float* src = st + r * 33 + q * 4;
            float4 v = {src[0], src[1], src[2], src[3]};
            *(float4*)(g_edge + (size_t)pos * 32 + q * 4) = v;
        }
    }
}

// ---------------- per-atom gather + hyper einsum + density ----------
// 2 atoms per block (128 threads = two 64-thread groups). Symmetric l=2:
// only 6 unique components carried; density weights {1,2,2,1,2,1} (exact —
// off-diagonal pairs are bitwise-equal through the whole recursion).
// Density phase loads each H value ONCE and applies it to BOTH atoms.
// PASS 0: WsumA = F; PASS 1: WsumB = WsumA + F; PASS 2: no Wsum write.
template <int PASS>
__global__ void __launch_bounds__(128, 6)
k_atom(const float* __restrict__ ef, const float* __restrict__ ef_para,
       const float* __restrict__ hyper, float* __restrict__ dens_final) {
    int tid = threadIdx.x;
    int ga = tid >> 6;                 // atom group 0/1
    int t = tid & 63;
    int i = blockIdx.x * 2 + ga;
    __shared__ float F_sh[2 * NFU];
    const float* WsumIn = (PASS == 1) ? g_WsumA : g_WsumB;
    float* WsumOut = (PASS == 0) ? g_WsumA : g_WsumB;
    int start = g_offset[i], end = g_offset[i + 1];

    // ---- gather: 40 of 64 threads accumulate (p=0..9, kq 4-wide) ----
    {
        int p = min(t >> 2, 9);
        int kq = (t & 3) << 2;
        int b = i >> 9;  // A = 512 atoms per batch
        float e0 = ef[b * 3], e1 = ef[b * 3 + 1], e2 = ef[b * 3 + 2];
        float angef;
        if (p == 0) angef = 1.f;
        else if (p < 4) angef = (p == 1) ? e0 : ((p == 2) ? e1 : e2);
        else {
            // unique pairs: 4:xx 5:xy 6:xz 7:yy 8:yz 9:zz
            float ua = (p < 7) ? e0 : ((p < 9) ? e1 : e2);
            float ub = (p == 4) ? e0 : (p == 5) ? e1 : (p == 6) ? e2 :
                       (p == 7) ? e1 : (p == 8) ? e2 : e2;
            angef = ua * ub;
        }
        float4 epr = *(const float4*)(ef_para + kq);
        float ax = angef * epr.x, ay = angef * epr.y;
        float az = angef * epr.z, aw = angef * epr.w;

        int4 nA = {0, 0, 0, 0}, nB = {0, 0, 0, 0};
        if (start < end) {
            nA = *(const int4*)(g_ejd + start);
            nB = *(const int4*)(g_ejd + start + 2);
        }
        for (int s = start; s < end; s += 4) {
            int4 cA = nA, cB = nB;
            int sn = s + 4;
            if (sn < end) {
                nA = *(const int4*)(g_ejd + sn);
                nB = *(const int4*)(g_ejd + sn + 2);
            }
            const float* edb = g_edge + (size_t)s * 32;
#pragma unroll
            for (int u = 0; u < 4; u++) {
                int j = (u == 0) ? cA.x : (u == 1) ? cA.z : (u == 2) ? cB.x : cB.z;
                float dcut = __int_as_float(
                    (u == 0) ? cA.y : (u == 1) ? cA.w : (u == 2) ? cB.y : cB.w);
                const float* ed = edb + u * 32;
                float ang = ed[2 + p];
                float4 rad = *(const float4*)(ed + 16 + kq);
                float4 cf = *(const float4*)(g_coeff + j * NW + kq);
                float ox = ang * rad.x, oy = ang * rad.y;
                float oz = ang * rad.z, ow = ang * rad.w;
                if (PASS > 0) {
                    float4 w = *(const float4*)(WsumIn + (size_t)j * NFU + p * 16 + kq);
                    ox += dcut * w.x; oy += dcut * w.y;
                    oz += dcut * w.z; ow += dcut * w.w;
                }
                ax += cf.x * ox; ay += cf.y * oy;
                az += cf.z * oz; aw += cf.w * ow;
            }
        }
        if (t < 40) {
            int fb = p * 16 + kq;
            float4 v = {ax, ay, az, aw};
            *(float4*)(F_sh + ga * NFU + fb) = v;
            if (PASS < 2) {
                float4 o = v;
                if (PASS == 1) {
                    float4 pr = *(const float4*)(WsumIn + (size_t)i * NFU + fb);
                    o.x += pr.x; o.y += pr.y; o.z += pr.z; o.w += pr.w;
                }
                *(float4*)(WsumOut + (size_t)i * NFU + fb) = o;
            }
        }
    }
    __syncthreads();

    // ---- density: 64 threads x 2 cols, BOTH atoms per H load ----
    if (tid < 64) {
        int m = tid * 2;
        int i0 = blockIdx.x * 2;
        float* dens_out = (PASS == 2) ? dens_final : g_density;
        const float* FA = F_sh;
        const float* FB = F_sh + NFU;
        float dxA = 0.f, dyA = 0.f, dxB = 0.f, dyB = 0.f;
        // l = 0 (p = 0), weight 1
        {
            float hxA = 0.f, hyA = 0.f, hxB = 0.f, hyB = 0.f;
#pragma unroll
            for (int kk = 0; kk < NW; kk++) {
                float2 h2 = *(const float2*)(hyper + kk * NORB + m);
                float eA = FA[kk], eB = FB[kk];
                hxA += eA * h2.x; hyA += eA * h2.y;
                hxB += eB * h2.x; hyB += eB * h2.y;
            }
            dxA += hxA * hxA; dyA += hyA * hyA;
            dxB += hxB * hxB; dyB += hyB * hyB;
        }
        // l = 1 (p = 1..3), weight 1
        {
            float hxA[3] = {0, 0, 0}, hyA[3] = {0, 0, 0};
            float hxB[3] = {0, 0, 0}, hyB[3] = {0, 0, 0};
#pragma unroll
            for (int kk = 0; kk < NW; kk++) {
                float2 h2 = *(const float2*)(hyper + NW * NORB + kk * NORB + m);
#pragma unroll
                for (int q = 0; q < 3; q++) {
                    float eA = FA[(1 + q) * NW + kk], eB = FB[(1 + q) * NW + kk];
                    hxA[q] += eA * h2.x; hyA[q] += eA * h2.y;
                    hxB[q] += eB * h2.x; hyB[q] += eB * h2.y;
                }
            }
#pragma unroll
            for (int q = 0; q < 3; q++) {
                dxA += hxA[q] * hxA[q]; dyA += hyA[q] * hyA[q];
                dxB += hxB[q] * hxB[q]; dyB += hyB[q] * hyB[q];
            }
        }
        // l = 2 unique (p = 4..9), weights {1,2,2,1,2,1}; 2 chunks of 3
#pragma unroll
        for (int g = 0; g < 2; g++) {
            float hxA[3] = {0, 0, 0}, hyA[3] = {0, 0, 0};
            float hxB[3] = {0, 0, 0}, hyB[3] = {0, 0, 0};
#pragma unroll
            for (int kk = 0; kk < NW; kk++) {
                float2 h2 = *(const float2*)(hyper + 2 * NW * NORB + kk * NORB + m);
#pragma unroll
                for (int q = 0; q < 3; q++) {
                    int pp = 4 + g * 3 + q;
                    float eA = FA[pp * NW + kk], eB = FB[pp * NW + kk];
                    hxA[q] += eA * h2.x; hyA[q] += eA * h2.y;
                    hxB[q] += eB * h2.x; hyB[q] += eB * h2.y;
                }
            }
#pragma unroll
            for (int q = 0; q < 3; q++) {
                // weights: idx 4:1 5:2 6:2 7:1 8:2 9:1
                int pp = 4 + g * 3 + q;
                float w = (pp == 5 || pp == 6 || pp == 8) ? 2.f : 1.f;
                dxA += w * hxA[q] * hxA[q]; dyA += w * hyA[q] * hyA[q];
                dxB += w * hxB[q] * hxB[q]; dyB += w * hyB[q] * hyB[q];
            }
        }
        float2 oA = {dxA, dyA};
        float2 oB = {dxB, dyB};
        *(float2*)(dens_out + (size_t)i0 * NORB + m) = oA;
        *(float2*)(dens_out + (size_t)(i0 + 1) * NORB + m) = oB;
    }
}

// ---------------- MLP: coeff += tanh(density@W1+b1)@W2 --------------
__global__ void __launch_bounds__(512)
k_mlp(const float* __restrict__ W1, const float* __restrict__ b1,
      const float* __restrict__ W2) {
    __shared__ float W1T[NHID * 132];   // 33 KB
    __shared__ float dsh[8 * NORB];     // 4 KB
    __shared__ float hsh[8 * NHID];     // 2 KB
    int tid = threadIdx.x;
    int i0 = blockIdx.x * 8;
    for (int idx = tid; idx < NORB * NHID; idx += 512) {
        int k = idx >> 6, h = idx & 63;
        W1T[h * 132 + k] = W1[idx];
    }
    for (int idx = tid; idx < 8 * NORB; idx += 512)
        dsh[idx] = g_density[(size_t)i0 * NORB + idx];
    __syncthreads();
    int a = tid >> 6, h = tid & 63;
    float acc = b1[h];
    const float4* w4 = (const float4*)(W1T + h * 132);
    const float4* d4 = (const float4*)(dsh + a * NORB);
#pragma unroll
    for (int q = 0; q < 32; q++) {
        float4 w = w4[q], d = d4[q];
        acc += w.x * d.x + w.y * d.y + w.z * d.z + w.w * d.w;
    }
    hsh[a * NHID + h] = tanhf(acc);
    __syncthreads();
    if (h < NW) {
        float delta = 0.f;
#pragma unroll
        for (int hh = 0; hh < NHID; hh++)
            delta += hsh[a * NHID + hh] * __ldg(&W2[hh * NW + h]);
        g_coeff[(i0 + a) * NW + h] += delta;
    }
}

// ---------------- launch --------------------------------------------
extern "C" void kernel_launch(void* const* d_in, const int* in_sizes, int n_in,
                              void* d_out, int out_size) {
    const float *cart = 0, *ef = 0, *shifts = 0, *ef_para = 0, *hyper = 0;
    const float *oc_w1 = 0, *oc_b1 = 0, *oc_w2 = 0;
    const int *neigh = 0, *species = 0;   // int32 (JAX x64 disabled)
    const float* trio[3] = {0, 0, 0};
    int ntrio = 0;
    for (int t = 0; t < n_in; t++) {
        int s = in_sizes[t];
        const void* p = d_in[t];
        switch (s) {
            case 24576:  cart    = (const float*)p; break;
            case 48:     ef      = (const float*)p; break;
            case 393216: shifts  = (const float*)p; break;
            case 16:     ef_para = (const float*)p; break;
            case 6144:   hyper   = (const float*)p; break;
            case 16384:  oc_w1   = (const float*)p; break;
            case 128:    oc_b1   = (const float*)p; break;
            case 2048:   oc_w2   = (const float*)p; break;
            case 262144: neigh   = (const int*)p; break;
            case 8192:   species = (const int*)p; break;
            case 64:     if (ntrio < 3) trio[ntrio++] = (const float*)p; break;
            default: break;
        }
    }
    if (!cart || !ef || !shifts || !ef_para || !hyper || !oc_w1 || !oc_b1 ||
        !oc_w2 || !neigh || !species || ntrio != 3) {
        cart    = (const float*)d_in[0];
        ef      = (const float*)d_in[1];
        shifts  = (const float*)d_in[2];
        trio[0] = (const float*)d_in[3];
        trio[1] = (const float*)d_in[4];
        trio[2] = (const float*)d_in[5];
        ef_para = (const float*)d_in[6];
        hyper   = (const float*)d_in[7];
        oc_w1   = (const float*)d_in[8];
        oc_b1   = (const float*)d_in[9];
        oc_w2   = (const float*)d_in[10];
        neigh   = (const int*)d_in[11];
        species = (const int*)d_in[12];
    }
    int E = EMAX;

    k_prep<<<(E + 255) / 256, 256>>>(trio[0], trio[1], trio[2], neigh, species, E);
    k_scan<<<1, 1024>>>();
    k_edges<<<(E + EB - 1) / EB, EB>>>(cart, shifts, species, neigh, E);

    k_atom<0><<<NATOM / 2, 128>>>(ef, ef_para, hyper, nullptr);   // 4th launch (ncu)
    k_mlp<<<NATOM / 8, 512>>>(oc_w1, oc_b1, oc_w2);
    k_atom<1><<<NATOM / 2, 128>>>(ef, ef_para, hyper, nullptr);
    k_mlp<<<NATOM / 8, 512>>>(oc_w1 + NORB * NHID, oc_b1 + NHID, oc_w2 + NHID * NW);
    k_atom<2><<<NATOM / 2, 128>>>(ef, ef_para, hyper, (float*)d_out);
}